// round 10
// baseline (speedup 1.0000x reference)
#include <cuda_runtime.h>
#include <cstdint>

#define B_SZ 512
#define IN_F 512
#define OUT_F 100
#define KD 5
#define KP 6                // padded kernel dim (row stride per o)
#define OCP 600             // OUT_F * KP, padded row stride
#define OC 500              // OUT_F * KD (unpadded, T layout)
#define LOG2E 1.4426950408889634f
#define NT 32               // number of batch tiles
#define TS 16               // tile size (NT*TS = B_SZ)
#define NP 528              // NT*(NT+1)/2 unordered tile pairs

// Scratch for M = (x @ T) * log2(e), padded layout [b][o*6+k], 1.2MB
__device__ float g_M[B_SZ * OCP];

__device__ __forceinline__ float ex2(float x) {
    float r;
    asm("ex2.approx.f32 %0, %1;" : "=f"(r) : "f"(x));
    return r;
}

// ---------------------------------------------------------------------------
// Kernel 1: M[b][o*6+k] = sum_i x[b][i] * T[i][o*5+k], scaled by log2e.
// L2-traffic-optimized: 16 b-rows per block halves T re-reads (32MB total,
// ~2.6us L2 floor). Block: 512 threads = 64 oc-pair-lanes x 8 K-slices (kh);
// each thread: 16 b x 2 oc accumulators over a 64-long K-slice. Grid (32,4)
// = 128 blocks = single wave. kh-slices tree-reduced via 32KB smem buffer.
// Epilogue writes padded layout. Also zeroes `out` (blockIdx.y == 0).
// ---------------------------------------------------------------------------
__global__ void __launch_bounds__(512, 2) gemm_kernel(const float* __restrict__ x,
                                                      const float* __restrict__ T,
                                                      float* __restrict__ out) {
    __shared__ __align__(16) float xs[IN_F * 16];          // [i][bb], 32KB
    __shared__ __align__(16) float red[4 * 16 * 128];      // 4 slices, 32KB

    const int t = threadIdx.x;
    const int lane = t & 63;               // oc-pair lane
    const int kh = t >> 6;                 // 0..7
    const int b0 = blockIdx.x * 16;
    const int oc0 = blockIdx.y * 128;
    const int oc = oc0 + lane * 2;
    const bool ocv = (oc < OC);

    if (blockIdx.y == 0) {
        for (int idx = blockIdx.x * 512 + t; idx < B_SZ * OUT_F; idx += 32 * 512)
            out[idx] = 0.0f;
    }

    // cooperative transpose load: x[b0+bb][i] -> xs[i*16+bb]
    for (int idx = t; idx < IN_F * 16; idx += 512) {
        int bb = idx >> 9;                 // 0..15
        int i = idx & (IN_F - 1);          // 0..511
        xs[i * 16 + bb] = x[(b0 + bb) * IN_F + i];
    }
    __syncthreads();

    float accx[16], accy[16];
#pragma unroll
    for (int bb = 0; bb < 16; bb++) { accx[bb] = 0.f; accy[bb] = 0.f; }

    if (ocv) {
        const float* tp = T + (size_t)(kh * 64) * OC + oc;
        const float* xp = xs + kh * 64 * 16;
#pragma unroll 4
        for (int i = 0; i < 64; i++) {
            float2 tv = *reinterpret_cast<const float2*>(tp + i * OC);
            const float4* row = reinterpret_cast<const float4*>(xp + i * 16);
            float4 xa = row[0];
            float4 xb = row[1];
            accx[0] += xa.x * tv.x; accy[0] += xa.x * tv.y;
            accx[1] += xa.y * tv.x; accy[1] += xa.y * tv.y;
            accx[2] += xa.z * tv.x; accy[2] += xa.z * tv.y;
            accx[3] += xa.w * tv.x; accy[3] += xa.w * tv.y;
            accx[4] += xb.x * tv.x; accy[4] += xb.x * tv.y;
            accx[5] += xb.y * tv.x; accy[5] += xb.y * tv.y;
            accx[6] += xb.z * tv.x; accy[6] += xb.z * tv.y;
            accx[7] += xb.w * tv.x; accy[7] += xb.w * tv.y;
            float4 xc = row[2];
            float4 xd = row[3];
            accx[8]  += xc.x * tv.x; accy[8]  += xc.x * tv.y;
            accx[9]  += xc.y * tv.x; accy[9]  += xc.y * tv.y;
            accx[10] += xc.z * tv.x; accy[10] += xc.z * tv.y;
            accx[11] += xc.w * tv.x; accy[11] += xc.w * tv.y;
            accx[12] += xd.x * tv.x; accy[12] += xd.x * tv.y;
            accx[13] += xd.y * tv.x; accy[13] += xd.y * tv.y;
            accx[14] += xd.z * tv.x; accy[14] += xd.z * tv.y;
            accx[15] += xd.w * tv.x; accy[15] += xd.w * tv.y;
        }
    }

    // tree reduction of 8 kh-slices (3 steps) through 4-slice buffer
    if (kh >= 4) {
        float* rp = red + (kh - 4) * 2048 + lane * 2;
#pragma unroll
        for (int bb = 0; bb < 16; bb++) { rp[bb * 128] = accx[bb]; rp[bb * 128 + 1] = accy[bb]; }
    }
    __syncthreads();
    if (kh < 4) {
        const float* rp = red + kh * 2048 + lane * 2;
#pragma unroll
        for (int bb = 0; bb < 16; bb++) { accx[bb] += rp[bb * 128]; accy[bb] += rp[bb * 128 + 1]; }
    }
    __syncthreads();
    if (kh == 2 || kh == 3) {
        float* rp = red + (kh - 2) * 2048 + lane * 2;
#pragma unroll
        for (int bb = 0; bb < 16; bb++) { rp[bb * 128] = accx[bb]; rp[bb * 128 + 1] = accy[bb]; }
    }
    __syncthreads();
    if (kh < 2) {
        const float* rp = red + kh * 2048 + lane * 2;
#pragma unroll
        for (int bb = 0; bb < 16; bb++) { accx[bb] += rp[bb * 128]; accy[bb] += rp[bb * 128 + 1]; }
    }
    __syncthreads();
    if (kh == 1) {
        float* rp = red + lane * 2;
#pragma unroll
        for (int bb = 0; bb < 16; bb++) { rp[bb * 128] = accx[bb]; rp[bb * 128 + 1] = accy[bb]; }
    }
    __syncthreads();
    if (kh == 0 && ocv) {
        // padded offsets for oc and oc+1
        const int o0 = oc / 5, k0 = oc - o0 * 5;
        const int oc1 = oc + 1;
        const int o1 = oc1 / 5, k1 = oc1 - o1 * 5;
#pragma unroll
        for (int bb = 0; bb < 16; bb++) {
            float sx = (accx[bb] + red[bb * 128 + lane * 2 + 0]) * LOG2E;
            float sy = (accy[bb] + red[bb * 128 + lane * 2 + 1]) * LOG2E;
            g_M[(size_t)(b0 + bb) * OCP + o0 * KP + k0] = sx;
            g_M[(size_t)(b0 + bb) * OCP + o1 * KP + k1] = sy;
        }
    }
}

// ---------------------------------------------------------------------------
// Kernel 2 (symmetric, padded vector loads — unchanged from R9 best):
// one block per unordered tile pair (ta <= tb), 528 blocks, 416 threads;
// t<400: o = t>>2, jl = t&3, JR=4. Padded KP=6 rows: d-loads 2x LDS.64 +
// 1x LDS.32 (conflict-free). occ-3.
// ---------------------------------------------------------------------------
__global__ void __launch_bounds__(416, 3) md_kernel(float* __restrict__ out) {
    __shared__ __align__(16) float ms[TS * OCP];  // 38.4KB

    int rem = blockIdx.x;
    int ta = 0;
    while (rem >= NT - ta) { rem -= NT - ta; ta++; }
    const int tb = ta + rem;
    const bool diag = (ta == tb);

    const int t = threadIdx.x;
    const bool act = (t < 400);
    const int o = act ? (t >> 2) : 99;
    const int jl = t & 3;

    // stage tile_a: 16 rows x 600 floats = 2400 float4
    {
        const float4* src = reinterpret_cast<const float4*>(g_M + (size_t)ta * TS * OCP);
        float4* dst = reinterpret_cast<float4*>(ms);
        for (int i = t; i < 2400; i += 416) dst[i] = src[i];
    }

    float a[4][5];
    float accJ[4];
#pragma unroll
    for (int r = 0; r < 4; r++) {
        const int j = tb * TS + jl + 4 * r;
        const float* m = g_M + (size_t)j * OCP + o * KP;
        float2 v01 = *reinterpret_cast<const float2*>(m);
        float2 v23 = *reinterpret_cast<const float2*>(m + 2);
        a[r][0] = v01.x; a[r][1] = v01.y;
        a[r][2] = v23.x; a[r][3] = v23.y;
        a[r][4] = m[4];
        accJ[r] = 0.f;
    }
    __syncthreads();

    const float* mp = ms + o * KP;

#pragma unroll
    for (int ii = 0; ii < TS; ii++) {
        const float* m = mp + ii * OCP;
        float2 d01 = *reinterpret_cast<const float2*>(m);
        float2 d23 = *reinterpret_cast<const float2*>(m + 2);
        float d4 = m[4];
        float loc = 0.f;
#pragma unroll
        for (int r = 0; r < 4; r++) {
            float pa = -fabsf(d01.x - a[r][0]) - fabsf(d01.y - a[r][1]);
            float qa = -fabsf(d23.x - a[r][2]) - fabsf(d23.y - a[r][3]);
            float n = (pa + qa) - fabsf(d4 - a[r][4]);
            float e = ex2(n);
            accJ[r] += e;
            loc += e;
        }
        if (!diag) {
            loc += __shfl_xor_sync(0xffffffffu, loc, 1);
            loc += __shfl_xor_sync(0xffffffffu, loc, 2);
            if (act && jl == 0)
                atomicAdd(&out[(ta * TS + ii) * OUT_F + o], loc);
        }
    }

    if (act) {
#pragma unroll
        for (int r = 0; r < 4; r++) {
            float v = accJ[r] - (diag ? 1.0f : 0.0f);
            atomicAdd(&out[(tb * TS + jl + 4 * r) * OUT_F + o], v);
        }
    }
}

extern "C" void kernel_launch(void* const* d_in, const int* in_sizes, int n_in,
                              void* d_out, int out_size) {
    const float* x = (const float*)d_in[0];   // [512, 512]
    const float* T = (const float*)d_in[1];   // [512, 100, 5] -> [512, 500]
    float* out = (float*)d_out;               // [512, 100]

    gemm_kernel<<<dim3(32, 4), 512>>>(x, T, out);
    md_kernel<<<NP, 416>>>(out);
}

// round 11
// speedup vs baseline: 1.0656x; 1.0656x over previous
#include <cuda_runtime.h>
#include <cstdint>

#define B_SZ 512
#define IN_F 512
#define OUT_F 100
#define KD 5
#define KP 6                // padded kernel dim (row stride per o)
#define OCP 600             // OUT_F * KP, padded row stride
#define OC 500              // OUT_F * KD (unpadded, T layout)
#define LOG2E 1.4426950408889634f
#define NT 32               // number of batch tiles
#define TS 16               // tile size (NT*TS = B_SZ)
#define NP 528              // NT*(NT+1)/2 unordered tile pairs

// Scratch for M = (x @ T) * log2(e), padded layout [b][o*6+k], 1.2MB
__device__ float g_M[B_SZ * OCP];

__device__ __forceinline__ float ex2(float x) {
    float r;
    asm("ex2.approx.f32 %0, %1;" : "=f"(r) : "f"(x));
    return r;
}

// ---------------------------------------------------------------------------
// Kernel 1 (proven R6/R7 config): M[b][o*6+k] = sum_i x[b][i]*T[i][o*5+k],
// scaled by log2e. 512 threads = 64 oc-pair-lanes x 8 K-slices; 8 b-rows per
// block; grid (64,4) = 256 blocks (full SM coverage). Tree-reduced via 16KB
// smem. Epilogue writes padded layout. Also zeroes `out` (blockIdx.y == 0).
// ---------------------------------------------------------------------------
__global__ void __launch_bounds__(512) gemm_kernel(const float* __restrict__ x,
                                                   const float* __restrict__ T,
                                                   float* __restrict__ out) {
    __shared__ __align__(16) float xs[IN_F * 8];          // [i][bb], 16KB
    __shared__ __align__(16) float red[4 * 8 * 128];      // 4 slices, 16KB

    const int t = threadIdx.x;
    const int lane = t & 63;               // oc-pair lane
    const int kh = t >> 6;                 // 0..7
    const int b0 = blockIdx.x * 8;
    const int oc0 = blockIdx.y * 128;
    const int oc = oc0 + lane * 2;
    const bool ocv = (oc < OC);

    if (blockIdx.y == 0) {
        for (int idx = blockIdx.x * 512 + t; idx < B_SZ * OUT_F; idx += 64 * 512)
            out[idx] = 0.0f;
    }

    // cooperative transpose load: x[b0+bb][i] -> xs[i*8+bb]
    for (int idx = t; idx < IN_F * 8; idx += 512) {
        int bb = idx >> 9;
        int i = idx & (IN_F - 1);
        xs[i * 8 + bb] = x[(b0 + bb) * IN_F + i];
    }
    __syncthreads();

    float accx0 = 0.f, accx1 = 0.f, accx2 = 0.f, accx3 = 0.f;
    float accx4 = 0.f, accx5 = 0.f, accx6 = 0.f, accx7 = 0.f;
    float accy0 = 0.f, accy1 = 0.f, accy2 = 0.f, accy3 = 0.f;
    float accy4 = 0.f, accy5 = 0.f, accy6 = 0.f, accy7 = 0.f;

    if (ocv) {
        const float* tp = T + (size_t)(kh * 64) * OC + oc;
        const float* xp = xs + kh * 64 * 8;
#pragma unroll 8
        for (int i = 0; i < 64; i++) {
            float2 tv = *reinterpret_cast<const float2*>(tp + i * OC);
            float4 xa = *reinterpret_cast<const float4*>(xp + i * 8);
            float4 xb = *reinterpret_cast<const float4*>(xp + i * 8 + 4);
            accx0 += xa.x * tv.x; accy0 += xa.x * tv.y;
            accx1 += xa.y * tv.x; accy1 += xa.y * tv.y;
            accx2 += xa.z * tv.x; accy2 += xa.z * tv.y;
            accx3 += xa.w * tv.x; accy3 += xa.w * tv.y;
            accx4 += xb.x * tv.x; accy4 += xb.x * tv.y;
            accx5 += xb.y * tv.x; accy5 += xb.y * tv.y;
            accx6 += xb.z * tv.x; accy6 += xb.z * tv.y;
            accx7 += xb.w * tv.x; accy7 += xb.w * tv.y;
        }
    }

#define STORE_RED(base)                                                        \
    do {                                                                       \
        float* rp = red + (base) * 1024 + lane * 2;                            \
        rp[0 * 128] = accx0; rp[0 * 128 + 1] = accy0;                          \
        rp[1 * 128] = accx1; rp[1 * 128 + 1] = accy1;                          \
        rp[2 * 128] = accx2; rp[2 * 128 + 1] = accy2;                          \
        rp[3 * 128] = accx3; rp[3 * 128 + 1] = accy3;                          \
        rp[4 * 128] = accx4; rp[4 * 128 + 1] = accy4;                          \
        rp[5 * 128] = accx5; rp[5 * 128 + 1] = accy5;                          \
        rp[6 * 128] = accx6; rp[6 * 128 + 1] = accy6;                          \
        rp[7 * 128] = accx7; rp[7 * 128 + 1] = accy7;                          \
    } while (0)
#define LOAD_RED(base)                                                         \
    do {                                                                       \
        const float* rp = red + (base) * 1024 + lane * 2;                      \
        accx0 += rp[0 * 128]; accy0 += rp[0 * 128 + 1];                        \
        accx1 += rp[1 * 128]; accy1 += rp[1 * 128 + 1];                        \
        accx2 += rp[2 * 128]; accy2 += rp[2 * 128 + 1];                        \
        accx3 += rp[3 * 128]; accy3 += rp[3 * 128 + 1];                        \
        accx4 += rp[4 * 128]; accy4 += rp[4 * 128 + 1];                        \
        accx5 += rp[5 * 128]; accy5 += rp[5 * 128 + 1];                        \
        accx6 += rp[6 * 128]; accy6 += rp[6 * 128 + 1];                        \
        accx7 += rp[7 * 128]; accy7 += rp[7 * 128 + 1];                        \
    } while (0)

    if (kh >= 4) STORE_RED(kh - 4);
    __syncthreads();
    if (kh < 4) LOAD_RED(kh);
    __syncthreads();
    if (kh == 2 || kh == 3) STORE_RED(kh - 2);
    __syncthreads();
    if (kh < 2) LOAD_RED(kh);
    __syncthreads();
    if (kh == 1) STORE_RED(0);
    __syncthreads();
    if (kh == 0) LOAD_RED(0);

    if (kh == 0 && ocv) {
        const int o0 = oc / 5, k0 = oc - o0 * 5;
        const int oc1 = oc + 1;
        const int o1 = oc1 / 5, k1 = oc1 - o1 * 5;
        const size_t off0 = (size_t)o0 * KP + k0;
        const size_t off1 = (size_t)o1 * KP + k1;
        g_M[(size_t)(b0 + 0) * OCP + off0] = accx0 * LOG2E;
        g_M[(size_t)(b0 + 0) * OCP + off1] = accy0 * LOG2E;
        g_M[(size_t)(b0 + 1) * OCP + off0] = accx1 * LOG2E;
        g_M[(size_t)(b0 + 1) * OCP + off1] = accy1 * LOG2E;
        g_M[(size_t)(b0 + 2) * OCP + off0] = accx2 * LOG2E;
        g_M[(size_t)(b0 + 2) * OCP + off1] = accy2 * LOG2E;
        g_M[(size_t)(b0 + 3) * OCP + off0] = accx3 * LOG2E;
        g_M[(size_t)(b0 + 3) * OCP + off1] = accy3 * LOG2E;
        g_M[(size_t)(b0 + 4) * OCP + off0] = accx4 * LOG2E;
        g_M[(size_t)(b0 + 4) * OCP + off1] = accy4 * LOG2E;
        g_M[(size_t)(b0 + 5) * OCP + off0] = accx5 * LOG2E;
        g_M[(size_t)(b0 + 5) * OCP + off1] = accy5 * LOG2E;
        g_M[(size_t)(b0 + 6) * OCP + off0] = accx6 * LOG2E;
        g_M[(size_t)(b0 + 6) * OCP + off1] = accy6 * LOG2E;
        g_M[(size_t)(b0 + 7) * OCP + off0] = accx7 * LOG2E;
        g_M[(size_t)(b0 + 7) * OCP + off1] = accy7 * LOG2E;
    }
#undef STORE_RED
#undef LOAD_RED
}

// ---------------------------------------------------------------------------
// Kernel 2 (symmetric, FULLY SCALARIZED j-state): one block per unordered
// tile pair (ta <= tb), 528 blocks, 416 threads; t<400: o = t>>2, jl = t&3,
// JR=4. All per-thread j-row values are named scalars (no indexed array ->
// guaranteed registers, no local-memory demotion). Padded KP=6 rows:
// d-loads 2x LDS.64 + 1x LDS.32, conflict-free. launch_bounds(416,2):
// 78-reg budget, ~45 live.
// ---------------------------------------------------------------------------
__global__ void __launch_bounds__(416, 2) md_kernel(float* __restrict__ out) {
    __shared__ __align__(16) float ms[TS * OCP];  // 38.4KB

    int rem = blockIdx.x;
    int ta = 0;
    while (rem >= NT - ta) { rem -= NT - ta; ta++; }
    const int tb = ta + rem;
    const bool diag = (ta == tb);

    const int t = threadIdx.x;
    const bool act = (t < 400);
    const int o = act ? (t >> 2) : 99;
    const int jl = t & 3;

    // stage tile_a: 16 rows x 600 floats = 2400 float4
    {
        const float4* src = reinterpret_cast<const float4*>(g_M + (size_t)ta * TS * OCP);
        float4* dst = reinterpret_cast<float4*>(ms);
        for (int i = t; i < 2400; i += 416) dst[i] = src[i];
    }

    // load 4 j-side rows into NAMED scalars
#define DECL_A(R)                                                              \
    float a##R##0, a##R##1, a##R##2, a##R##3, a##R##4;                         \
    {                                                                          \
        const int j = tb * TS + jl + 4 * (R);                                  \
        const float* m = g_M + (size_t)j * OCP + o * KP;                       \
        float2 v01 = *reinterpret_cast<const float2*>(m);                      \
        float2 v23 = *reinterpret_cast<const float2*>(m + 2);                  \
        a##R##0 = v01.x; a##R##1 = v01.y;                                      \
        a##R##2 = v23.x; a##R##3 = v23.y;                                      \
        a##R##4 = m[4];                                                        \
    }
    DECL_A(0)
    DECL_A(1)
    DECL_A(2)
    DECL_A(3)
#undef DECL_A

    float accJ0 = 0.f, accJ1 = 0.f, accJ2 = 0.f, accJ3 = 0.f;

    __syncthreads();

    const float* mp = ms + o * KP;

#define EVAL(R, ACC)                                                           \
    {                                                                          \
        float pa = -fabsf(d01.x - a##R##0) - fabsf(d01.y - a##R##1);           \
        float qa = -fabsf(d23.x - a##R##2) - fabsf(d23.y - a##R##3);           \
        float n = (pa + qa) - fabsf(d4 - a##R##4);                             \
        float e = ex2(n);                                                      \
        ACC += e;                                                              \
        loc += e;                                                              \
    }

#pragma unroll
    for (int ii = 0; ii < TS; ii++) {
        const float* m = mp + ii * OCP;
        float2 d01 = *reinterpret_cast<const float2*>(m);
        float2 d23 = *reinterpret_cast<const float2*>(m + 2);
        float d4 = m[4];
        float loc = 0.f;
        EVAL(0, accJ0)
        EVAL(1, accJ1)
        EVAL(2, accJ2)
        EVAL(3, accJ3)
        if (!diag) {
            loc += __shfl_xor_sync(0xffffffffu, loc, 1);
            loc += __shfl_xor_sync(0xffffffffu, loc, 2);
            if (act && jl == 0)
                atomicAdd(&out[(ta * TS + ii) * OUT_F + o], loc);
        }
    }
#undef EVAL

    if (act) {
        const float sub = diag ? 1.0f : 0.0f;
        atomicAdd(&out[(tb * TS + jl + 0)  * OUT_F + o], accJ0 - sub);
        atomicAdd(&out[(tb * TS + jl + 4)  * OUT_F + o], accJ1 - sub);
        atomicAdd(&out[(tb * TS + jl + 8)  * OUT_F + o], accJ2 - sub);
        atomicAdd(&out[(tb * TS + jl + 12) * OUT_F + o], accJ3 - sub);
    }
}

extern "C" void kernel_launch(void* const* d_in, const int* in_sizes, int n_in,
                              void* d_out, int out_size) {
    const float* x = (const float*)d_in[0];   // [512, 512]
    const float* T = (const float*)d_in[1];   // [512, 100, 5] -> [512, 500]
    float* out = (float*)d_out;               // [512, 100]

    gemm_kernel<<<dim3(64, 4), 512>>>(x, T, out);
    md_kernel<<<NP, 416>>>(out);
}

// round 12
// speedup vs baseline: 1.0667x; 1.0010x over previous
#include <cuda_runtime.h>
#include <cstdint>

#define B_SZ 512
#define IN_F 512
#define OUT_F 100
#define KD 5
#define KP 6                // padded kernel dim (row stride per o)
#define OCP 600             // OUT_F * KP, padded row stride
#define OC 500              // OUT_F * KD (unpadded, T layout)
#define LOG2E 1.4426950408889634f
#define NT 32               // number of batch tiles
#define TS 16               // tile size (NT*TS = B_SZ)
#define NP 528              // NT*(NT+1)/2 unordered tile pairs

// Scratch for M = (x @ T) * log2(e), padded layout [b][o*6+k], 1.2MB
__device__ float g_M[B_SZ * OCP];

__device__ __forceinline__ float ex2(float x) {
    float r;
    asm("ex2.approx.f32 %0, %1;" : "=f"(r) : "f"(x));
    return r;
}

// ---------------------------------------------------------------------------
// Kernel 1 (unchanged from R11): M[b][o*6+k] = sum_i x[b][i]*T[i][o*5+k],
// scaled by log2e. 512 threads = 64 oc-pair-lanes x 8 K-slices; 8 b-rows per
// block; grid (64,4) = 256 blocks. Tree-reduced via smem. Padded epilogue.
// Also zeroes `out` (blockIdx.y == 0).
// ---------------------------------------------------------------------------
__global__ void __launch_bounds__(512) gemm_kernel(const float* __restrict__ x,
                                                   const float* __restrict__ T,
                                                   float* __restrict__ out) {
    __shared__ __align__(16) float xs[IN_F * 8];          // [i][bb], 16KB
    __shared__ __align__(16) float red[4 * 8 * 128];      // 4 slices, 16KB

    const int t = threadIdx.x;
    const int lane = t & 63;
    const int kh = t >> 6;
    const int b0 = blockIdx.x * 8;
    const int oc0 = blockIdx.y * 128;
    const int oc = oc0 + lane * 2;
    const bool ocv = (oc < OC);

    if (blockIdx.y == 0) {
        for (int idx = blockIdx.x * 512 + t; idx < B_SZ * OUT_F; idx += 64 * 512)
            out[idx] = 0.0f;
    }

    for (int idx = t; idx < IN_F * 8; idx += 512) {
        int bb = idx >> 9;
        int i = idx & (IN_F - 1);
        xs[i * 8 + bb] = x[(b0 + bb) * IN_F + i];
    }
    __syncthreads();

    float accx0 = 0.f, accx1 = 0.f, accx2 = 0.f, accx3 = 0.f;
    float accx4 = 0.f, accx5 = 0.f, accx6 = 0.f, accx7 = 0.f;
    float accy0 = 0.f, accy1 = 0.f, accy2 = 0.f, accy3 = 0.f;
    float accy4 = 0.f, accy5 = 0.f, accy6 = 0.f, accy7 = 0.f;

    if (ocv) {
        const float* tp = T + (size_t)(kh * 64) * OC + oc;
        const float* xp = xs + kh * 64 * 8;
#pragma unroll 8
        for (int i = 0; i < 64; i++) {
            float2 tv = *reinterpret_cast<const float2*>(tp + i * OC);
            float4 xa = *reinterpret_cast<const float4*>(xp + i * 8);
            float4 xb = *reinterpret_cast<const float4*>(xp + i * 8 + 4);
            accx0 += xa.x * tv.x; accy0 += xa.x * tv.y;
            accx1 += xa.y * tv.x; accy1 += xa.y * tv.y;
            accx2 += xa.z * tv.x; accy2 += xa.z * tv.y;
            accx3 += xa.w * tv.x; accy3 += xa.w * tv.y;
            accx4 += xb.x * tv.x; accy4 += xb.x * tv.y;
            accx5 += xb.y * tv.x; accy5 += xb.y * tv.y;
            accx6 += xb.z * tv.x; accy6 += xb.z * tv.y;
            accx7 += xb.w * tv.x; accy7 += xb.w * tv.y;
        }
    }

#define STORE_RED(base)                                                        \
    do {                                                                       \
        float* rp = red + (base) * 1024 + lane * 2;                            \
        rp[0 * 128] = accx0; rp[0 * 128 + 1] = accy0;                          \
        rp[1 * 128] = accx1; rp[1 * 128 + 1] = accy1;                          \
        rp[2 * 128] = accx2; rp[2 * 128 + 1] = accy2;                          \
        rp[3 * 128] = accx3; rp[3 * 128 + 1] = accy3;                          \
        rp[4 * 128] = accx4; rp[4 * 128 + 1] = accy4;                          \
        rp[5 * 128] = accx5; rp[5 * 128 + 1] = accy5;                          \
        rp[6 * 128] = accx6; rp[6 * 128 + 1] = accy6;                          \
        rp[7 * 128] = accx7; rp[7 * 128 + 1] = accy7;                          \
    } while (0)
#define LOAD_RED(base)                                                         \
    do {                                                                       \
        const float* rp = red + (base) * 1024 + lane * 2;                      \
        accx0 += rp[0 * 128]; accy0 += rp[0 * 128 + 1];                        \
        accx1 += rp[1 * 128]; accy1 += rp[1 * 128 + 1];                        \
        accx2 += rp[2 * 128]; accy2 += rp[2 * 128 + 1];                        \
        accx3 += rp[3 * 128]; accy3 += rp[3 * 128 + 1];                        \
        accx4 += rp[4 * 128]; accy4 += rp[4 * 128 + 1];                        \
        accx5 += rp[5 * 128]; accy5 += rp[5 * 128 + 1];                        \
        accx6 += rp[6 * 128]; accy6 += rp[6 * 128 + 1];                        \
        accx7 += rp[7 * 128]; accy7 += rp[7 * 128 + 1];                        \
    } while (0)

    if (kh >= 4) STORE_RED(kh - 4);
    __syncthreads();
    if (kh < 4) LOAD_RED(kh);
    __syncthreads();
    if (kh == 2 || kh == 3) STORE_RED(kh - 2);
    __syncthreads();
    if (kh < 2) LOAD_RED(kh);
    __syncthreads();
    if (kh == 1) STORE_RED(0);
    __syncthreads();
    if (kh == 0) LOAD_RED(0);

    if (kh == 0 && ocv) {
        const int o0 = oc / 5, k0 = oc - o0 * 5;
        const int oc1 = oc + 1;
        const int o1 = oc1 / 5, k1 = oc1 - o1 * 5;
        const size_t off0 = (size_t)o0 * KP + k0;
        const size_t off1 = (size_t)o1 * KP + k1;
        g_M[(size_t)(b0 + 0) * OCP + off0] = accx0 * LOG2E;
        g_M[(size_t)(b0 + 0) * OCP + off1] = accy0 * LOG2E;
        g_M[(size_t)(b0 + 1) * OCP + off0] = accx1 * LOG2E;
        g_M[(size_t)(b0 + 1) * OCP + off1] = accy1 * LOG2E;
        g_M[(size_t)(b0 + 2) * OCP + off0] = accx2 * LOG2E;
        g_M[(size_t)(b0 + 2) * OCP + off1] = accy2 * LOG2E;
        g_M[(size_t)(b0 + 3) * OCP + off0] = accx3 * LOG2E;
        g_M[(size_t)(b0 + 3) * OCP + off1] = accy3 * LOG2E;
        g_M[(size_t)(b0 + 4) * OCP + off0] = accx4 * LOG2E;
        g_M[(size_t)(b0 + 4) * OCP + off1] = accy4 * LOG2E;
        g_M[(size_t)(b0 + 5) * OCP + off0] = accx5 * LOG2E;
        g_M[(size_t)(b0 + 5) * OCP + off1] = accy5 * LOG2E;
        g_M[(size_t)(b0 + 6) * OCP + off0] = accx6 * LOG2E;
        g_M[(size_t)(b0 + 6) * OCP + off1] = accy6 * LOG2E;
        g_M[(size_t)(b0 + 7) * OCP + off0] = accx7 * LOG2E;
        g_M[(size_t)(b0 + 7) * OCP + off1] = accy7 * LOG2E;
    }
#undef STORE_RED
#undef LOAD_RED
}

// ---------------------------------------------------------------------------
// Kernel 2 (symmetric, BRANCHLESS hot loop): one block per unordered tile
// pair, 528 blocks, 416 threads; t<400: o = t>>2, jl = t&3, JR=4.
// The 16-deep ii loop is pure straight-line code: 3 LDS + 4 evals + 1 reg
// store per ii — NO shfl, NO atomics, NO divergence regions (and thus no
// per-iteration BSSY/BSYNC convergence stalls). Transpose sums accumulate
// into 16 compile-time-indexed registers accI[]; the 4-lane butterfly
// reduction, jl-selection (compile-time SELs) and all atomics run once in
// the epilogue.
// ---------------------------------------------------------------------------
__global__ void __launch_bounds__(416, 2) md_kernel(float* __restrict__ out) {
    __shared__ __align__(16) float ms[TS * OCP];  // 38.4KB

    int rem = blockIdx.x;
    int ta = 0;
    while (rem >= NT - ta) { rem -= NT - ta; ta++; }
    const int tb = ta + rem;
    const bool diag = (ta == tb);

    const int t = threadIdx.x;
    const bool act = (t < 400);
    const int o = act ? (t >> 2) : 99;
    const int jl = t & 3;

    // stage tile_a: 16 rows x 600 floats = 2400 float4
    {
        const float4* src = reinterpret_cast<const float4*>(g_M + (size_t)ta * TS * OCP);
        float4* dst = reinterpret_cast<float4*>(ms);
        for (int i = t; i < 2400; i += 416) dst[i] = src[i];
    }

    // load 4 j-side rows into NAMED scalars
#define DECL_A(R)                                                              \
    float a##R##0, a##R##1, a##R##2, a##R##3, a##R##4;                         \
    {                                                                          \
        const int j = tb * TS + jl + 4 * (R);                                  \
        const float* m = g_M + (size_t)j * OCP + o * KP;                       \
        float2 v01 = *reinterpret_cast<const float2*>(m);                      \
        float2 v23 = *reinterpret_cast<const float2*>(m + 2);                  \
        a##R##0 = v01.x; a##R##1 = v01.y;                                      \
        a##R##2 = v23.x; a##R##3 = v23.y;                                      \
        a##R##4 = m[4];                                                        \
    }
    DECL_A(0)
    DECL_A(1)
    DECL_A(2)
    DECL_A(3)
#undef DECL_A

    float accJ0 = 0.f, accJ1 = 0.f, accJ2 = 0.f, accJ3 = 0.f;
    float accI[TS];   // compile-time indexed only -> stays in registers
#pragma unroll
    for (int ii = 0; ii < TS; ii++) accI[ii] = 0.f;

    __syncthreads();

    const float* mp = ms + o * KP;

#define EVAL(R, ACC)                                                           \
    {                                                                          \
        float pa = -fabsf(d01.x - a##R##0) - fabsf(d01.y - a##R##1);           \
        float qa = -fabsf(d23.x - a##R##2) - fabsf(d23.y - a##R##3);           \
        float n = (pa + qa) - fabsf(d4 - a##R##4);                             \
        float e = ex2(n);                                                      \
        ACC += e;                                                              \
        loc += e;                                                              \
    }

#pragma unroll
    for (int ii = 0; ii < TS; ii++) {
        const float* m = mp + ii * OCP;
        float2 d01 = *reinterpret_cast<const float2*>(m);
        float2 d23 = *reinterpret_cast<const float2*>(m + 2);
        float d4 = m[4];
        float loc = 0.f;
        EVAL(0, accJ0)
        EVAL(1, accJ1)
        EVAL(2, accJ2)
        EVAL(3, accJ3)
        accI[ii] = loc;
    }
#undef EVAL

    // Epilogue: butterfly-reduce each accI[ii] across the 4 jl-lanes
    // (all 32 lanes participate; groups of 4 share the same o).
#pragma unroll
    for (int ii = 0; ii < TS; ii++) {
        float v = accI[ii];
        v += __shfl_xor_sync(0xffffffffu, v, 1);
        v += __shfl_xor_sync(0xffffffffu, v, 2);
        accI[ii] = v;   // now = sum over all 16 j's of this block, for row ii
    }

    if (act) {
        if (!diag) {
            // lane jl writes rows ii = jl*4 + q (q = 0..3); select with
            // compile-time indices only (no dynamic register indexing)
#pragma unroll
            for (int q = 0; q < 4; q++) {
                float v = (jl == 0) ? accI[q]
                        : (jl == 1) ? accI[4 + q]
                        : (jl == 2) ? accI[8 + q]
                                    : accI[12 + q];
                const int ii = jl * 4 + q;
                atomicAdd(&out[(ta * TS + ii) * OUT_F + o], v);
            }
        }
        const float sub = diag ? 1.0f : 0.0f;
        atomicAdd(&out[(tb * TS + jl + 0)  * OUT_F + o], accJ0 - sub);
        atomicAdd(&out[(tb * TS + jl + 4)  * OUT_F + o], accJ1 - sub);
        atomicAdd(&out[(tb * TS + jl + 8)  * OUT_F + o], accJ2 - sub);
        atomicAdd(&out[(tb * TS + jl + 12) * OUT_F + o], accJ3 - sub);
    }
}

extern "C" void kernel_launch(void* const* d_in, const int* in_sizes, int n_in,
                              void* d_out, int out_size) {
    const float* x = (const float*)d_in[0];   // [512, 512]
    const float* T = (const float*)d_in[1];   // [512, 100, 5] -> [512, 500]
    float* out = (float*)d_out;               // [512, 100]

    gemm_kernel<<<dim3(64, 4), 512>>>(x, T, out);
    md_kernel<<<NP, 416>>>(out);
}